// round 1
// baseline (speedup 1.0000x reference)
#include <cuda_runtime.h>
#include <math.h>

#define NN   2
#define HH   16
#define TT   4096
#define DD   64
#define BS   128
#define NB   (TT / BS)          // 32
#define NEGV -3.402823466e38f
#define PQK  129                // odd pitch for transposed Q/K tiles (bank-conflict-free)
#define PP   129                // odd pitch for P tile

// smem floats: Qs 64*129, Ks 64*129, Vs 128*64, Ps 128*129, k0 64, v0 64, msk 128
#define SMEM_FLOATS (64*PQK + 64*PQK + 128*64 + 128*PP + 64 + 64 + 128)

// ---------------------------------------------------------------------------
// Kernel 1: block-local attention. One CTA per (block, head, batch).
// 256 threads = 16x16; thread (ty,tx): queries q = ty*8 + i (i<8),
// keys k = tx + 16*j (j<8), output dims dcol = tx*4 + j (j<4).
// ---------------------------------------------------------------------------
__global__ __launch_bounds__(256, 1)
void bla_local_kernel(const float* __restrict__ Q, const float* __restrict__ K,
                      const float* __restrict__ V, const float* __restrict__ M,
                      float* __restrict__ O)
{
    extern __shared__ float sm[];
    float* Qs   = sm;                    // [64][PQK]  transposed: Qs[dd][q]
    float* Ks   = Qs + 64 * PQK;         // [64][PQK]  transposed: Ks[dd][p]
    float* Vs   = Ks + 64 * PQK;         // [128][64]
    float* Ps   = Vs + 128 * 64;         // [128][PP]
    float* k0s  = Ps + 128 * PP;         // [64]
    float* v0s  = k0s + 64;              // [64]
    float* msks = v0s + 64;              // [128]

    const int b = blockIdx.x, h = blockIdx.y, n = blockIdx.z;
    const int tid = threadIdx.x;
    const int tx = tid & 15, ty = tid >> 4;

    const size_t nh = (size_t)n * HH + h;
    const float* Qb = Q + (nh * TT + (size_t)b * BS) * DD;
    const float* Kb = K + nh * TT * DD;
    const float* Vb = V + nh * TT * DD;
    const float* Mb = M + (size_t)n * TT;
    float*       Ob = O + (nh * TT + (size_t)b * BS) * DD;

    // ---- Stage Q tile transposed into smem; stage k0/v0 -------------------
    {
        const int r  = tid >> 4;           // row within 16-row chunk
        const int c4 = (tid & 15) * 4;     // starting dd
        #pragma unroll
        for (int it = 0; it < 8; it++) {
            const int q = r + it * 16;
            float4 v = *(const float4*)(Qb + q * DD + c4);
            Qs[(c4 + 0) * PQK + q] = v.x;
            Qs[(c4 + 1) * PQK + q] = v.y;
            Qs[(c4 + 2) * PQK + q] = v.z;
            Qs[(c4 + 3) * PQK + q] = v.w;
        }
    }
    if (tid < 64)       k0s[tid]      = Kb[tid];
    else if (tid < 128) v0s[tid - 64] = Vb[tid - 64];
    __syncthreads();

    float m[8], l[8], acc[8][4];

    // ---- Init online softmax with the global key (key 0, mask 0) ----------
    {
        float s0[8];
        #pragma unroll
        for (int i = 0; i < 8; i++) s0[i] = 0.f;
        #pragma unroll 4
        for (int dd = 0; dd < 64; dd++) {
            const float kv = k0s[dd];
            const float* qr = Qs + dd * PQK + ty * 8;
            #pragma unroll
            for (int i = 0; i < 8; i++) s0[i] += qr[i] * kv;
        }
        #pragma unroll
        for (int i = 0; i < 8; i++) {
            m[i] = s0[i] * 0.125f;
            l[i] = 1.f;
            #pragma unroll
            for (int j = 0; j < 4; j++) acc[i][j] = v0s[tx * 4 + j];
        }
    }

    // ---- 3 key tiles: blocks b-1, b, b+1 ----------------------------------
    for (int kt = 0; kt < 3; kt++) {
        const int blk = b + kt - 1;
        if (blk < 0 || blk >= NB) continue;     // fully out-of-range tiles
        const int p0 = blk * BS;

        // load K tile (transposed) + V tile + mask row
        {
            const int r  = tid >> 4;
            const int c4 = (tid & 15) * 4;
            #pragma unroll
            for (int it = 0; it < 8; it++) {
                const int p = r + it * 16;
                float4 kv = *(const float4*)(Kb + (size_t)(p0 + p) * DD + c4);
                Ks[(c4 + 0) * PQK + p] = kv.x;
                Ks[(c4 + 1) * PQK + p] = kv.y;
                Ks[(c4 + 2) * PQK + p] = kv.z;
                Ks[(c4 + 3) * PQK + p] = kv.w;
                float4 vv = *(const float4*)(Vb + (size_t)(p0 + p) * DD + c4);
                *(float4*)(Vs + p * 64 + c4) = vv;
            }
        }
        if (tid < 128) {
            const int p = p0 + tid;
            msks[tid] = (p == 0) ? NEGV : Mb[p];
        }
        __syncthreads();

        // S = Q K^T  (8x8 per thread, keys k = tx + 16*j)
        float s[8][8];
        #pragma unroll
        for (int i = 0; i < 8; i++)
            #pragma unroll
            for (int j = 0; j < 8; j++) s[i][j] = 0.f;

        #pragma unroll 4
        for (int dd = 0; dd < 64; dd++) {
            const float* qr = Qs + dd * PQK + ty * 8;
            const float* kr = Ks + dd * PQK + tx;
            float a[8], bb[8];
            #pragma unroll
            for (int i = 0; i < 8; i++) a[i]  = qr[i];
            #pragma unroll
            for (int j = 0; j < 8; j++) bb[j] = kr[16 * j];
            #pragma unroll
            for (int i = 0; i < 8; i++)
                #pragma unroll
                for (int j = 0; j < 8; j++) s[i][j] += a[i] * bb[j];
        }

        // mask values for this thread's key columns
        float mk[8];
        #pragma unroll
        for (int j = 0; j < 8; j++) mk[j] = msks[tx + 16 * j];

        // scale + mask + online softmax update + write P tile
        #pragma unroll
        for (int i = 0; i < 8; i++) {
            float tmax = NEGV;
            #pragma unroll
            for (int j = 0; j < 8; j++) {
                s[i][j] = s[i][j] * 0.125f + mk[j];
                tmax = fmaxf(tmax, s[i][j]);
            }
            #pragma unroll
            for (int o = 1; o < 16; o <<= 1)
                tmax = fmaxf(tmax, __shfl_xor_sync(0xffffffffu, tmax, o));
            const float mn   = fmaxf(m[i], tmax);
            const float corr = __expf(m[i] - mn);
            float rs = 0.f;
            #pragma unroll
            for (int j = 0; j < 8; j++) {
                const float p_ = __expf(s[i][j] - mn);
                s[i][j] = p_;
                rs += p_;
            }
            #pragma unroll
            for (int o = 1; o < 16; o <<= 1)
                rs += __shfl_xor_sync(0xffffffffu, rs, o);
            l[i] = l[i] * corr + rs;
            m[i] = mn;
            #pragma unroll
            for (int j = 0; j < 4; j++) acc[i][j] *= corr;
            float* pr = Ps + (ty * 8 + i) * PP + tx;
            #pragma unroll
            for (int j = 0; j < 8; j++) pr[16 * j] = s[i][j];
        }
        __syncthreads();

        // O += P V   (dims dcol = tx*4 + j)
        #pragma unroll 4
        for (int kk = 0; kk < 128; kk++) {
            const float4 vv = *(const float4*)(Vs + kk * 64 + tx * 4);
            const float* pc = Ps + (ty * 8) * PP + kk;
            #pragma unroll
            for (int i = 0; i < 8; i++) {
                const float pp = pc[i * PP];
                acc[i][0] += pp * vv.x;
                acc[i][1] += pp * vv.y;
                acc[i][2] += pp * vv.z;
                acc[i][3] += pp * vv.w;
            }
        }
        __syncthreads();
    }

    // ---- epilogue ----------------------------------------------------------
    #pragma unroll
    for (int i = 0; i < 8; i++) {
        const float inv = 1.f / l[i];
        float4 o4 = make_float4(acc[i][0] * inv, acc[i][1] * inv,
                                acc[i][2] * inv, acc[i][3] * inv);
        *(float4*)(Ob + (ty * 8 + i) * DD + tx * 4) = o4;
    }
}

// ---------------------------------------------------------------------------
// Kernel 2: global row — out[n,h,0,:] = softmax(q0 K^T * scale + mask) V
// over all 4096 keys. One CTA per (h, n). Must run AFTER kernel 1.
// ---------------------------------------------------------------------------
__global__ __launch_bounds__(256)
void bla_global_kernel(const float* __restrict__ Q, const float* __restrict__ K,
                       const float* __restrict__ V, const float* __restrict__ M,
                       float* __restrict__ O)
{
    __shared__ float q0[64];
    __shared__ float sc[TT];        // 16 KB
    __shared__ float red[256];
    __shared__ float opart[4][64];

    const int h = blockIdx.x, n = blockIdx.y;
    const int tid = threadIdx.x;
    const size_t nh = (size_t)n * HH + h;
    const float* Qb = Q + nh * TT * DD;
    const float* Kb = K + nh * TT * DD;
    const float* Vb = V + nh * TT * DD;
    const float* Mb = M + (size_t)n * TT;

    if (tid < 64) q0[tid] = Qb[tid];
    __syncthreads();

    const int lane = tid & 31, w = tid >> 5;
    const float qa = q0[lane], qb = q0[lane + 32];

    // scores: one key per warp iteration, shuffle-reduced
    #pragma unroll 4
    for (int p = w; p < TT; p += 8) {
        float x = qa * Kb[(size_t)p * DD + lane] + qb * Kb[(size_t)p * DD + lane + 32];
        #pragma unroll
        for (int o = 16; o; o >>= 1) x += __shfl_xor_sync(0xffffffffu, x, o);
        if (lane == 0) sc[p] = x * 0.125f + Mb[p];
    }
    __syncthreads();

    // block max
    float mx = NEGV;
    for (int p = tid; p < TT; p += 256) mx = fmaxf(mx, sc[p]);
    red[tid] = mx; __syncthreads();
    for (int s = 128; s; s >>= 1) {
        if (tid < s) red[tid] = fmaxf(red[tid], red[tid + s]);
        __syncthreads();
    }
    const float mall = red[0];
    __syncthreads();

    // exp + sum
    float sme = 0.f;
    for (int p = tid; p < TT; p += 256) {
        const float e = __expf(sc[p] - mall);
        sc[p] = e;
        sme += e;
    }
    red[tid] = sme; __syncthreads();
    for (int s = 128; s; s >>= 1) {
        if (tid < s) red[tid] += red[tid + s];
        __syncthreads();
    }
    const float linv = 1.f / red[0];

    // O = sum_p prob[p] * V[p][:]
    const int dd = tid & 63, seg = tid >> 6;
    float o = 0.f;
    #pragma unroll 8
    for (int p = seg * (TT / 4); p < (seg + 1) * (TT / 4); p++)
        o += sc[p] * Vb[(size_t)p * DD + dd];
    opart[seg][dd] = o;
    __syncthreads();
    if (tid < 64) {
        const float r = (opart[0][tid] + opart[1][tid] +
                         opart[2][tid] + opart[3][tid]) * linv;
        O[nh * TT * DD + tid] = r;
    }
}

// ---------------------------------------------------------------------------
extern "C" void kernel_launch(void* const* d_in, const int* in_sizes, int n_in,
                              void* d_out, int out_size)
{
    (void)in_sizes; (void)n_in; (void)out_size;
    const float* Q = (const float*)d_in[0];
    const float* K = (const float*)d_in[1];
    const float* V = (const float*)d_in[2];
    const float* M = (const float*)d_in[3];
    float* O = (float*)d_out;

    const size_t smem = SMEM_FLOATS * sizeof(float);   // ~166 KB
    cudaFuncSetAttribute(bla_local_kernel,
                         cudaFuncAttributeMaxDynamicSharedMemorySize, (int)smem);

    bla_local_kernel<<<dim3(NB, HH, NN), 256, smem>>>(Q, K, V, M, O);
    bla_global_kernel<<<dim3(HH, NN), 256>>>(Q, K, V, M, O);
}

// round 2
// speedup vs baseline: 1.7596x; 1.7596x over previous
#include <cuda_runtime.h>
#include <math.h>

#define NN   2
#define HH   16
#define TT   4096
#define DD   64
#define BS   128
#define NB   (TT / BS)          // 32
#define NCH  32                 // key chunks for global row split-K
#define NEGV -3.402823466e38f
#define PQK  130                // even pitch: LDS.64-aligned transposed Q/K tiles
#define PP   129                // odd pitch for P tile (scalar access only)

// smem floats: Qs 64*130, Ks 64*130, Vs 128*64, Ps 128*129, k0 64, v0 64, msk 128
#define SMEM_FLOATS (64*PQK + 64*PQK + 128*64 + 128*PP + 64 + 64 + 128)

typedef unsigned long long u64t;

// scratch for global-row split-K partials: [n][h][chunk][2 + 64]
__device__ float g_part[NN * HH * NCH * 66];

// ---- f32x2 packed helpers --------------------------------------------------
__device__ __forceinline__ u64t pack2(float lo, float hi) {
    u64t r;
    asm("mov.b64 %0, {%1, %2};" : "=l"(r) : "f"(lo), "f"(hi));
    return r;
}
__device__ __forceinline__ void unpack2(u64t v, float& lo, float& hi) {
    asm("mov.b64 {%0, %1}, %2;" : "=f"(lo), "=f"(hi) : "l"(v));
}
__device__ __forceinline__ void fma2(u64t& d, u64t a, u64t b) {
    asm("fma.rn.f32x2 %0, %1, %2, %0;" : "+l"(d) : "l"(a), "l"(b));
}
__device__ __forceinline__ void mul2(u64t& d, u64t a) {
    asm("mul.rn.f32x2 %0, %0, %1;" : "+l"(d) : "l"(a));
}

// ---------------------------------------------------------------------------
// Kernel 1: block-local attention. One CTA per (block, head, batch).
// 256 threads = 16x16; thread (ty,tx): queries q = ty*8 + i (i<8),
// keys k = tx + 16*j (j<8), output dims dcol = tx*4 + j (j<4).
// QK^T packed over query pairs; PV packed over dim pairs (fma.rn.f32x2).
// ---------------------------------------------------------------------------
__global__ __launch_bounds__(256, 1)
void bla_local_kernel(const float* __restrict__ Q, const float* __restrict__ K,
                      const float* __restrict__ V, const float* __restrict__ M,
                      float* __restrict__ O)
{
    extern __shared__ float sm[];
    float* Qs   = sm;                    // [64][PQK]  transposed: Qs[dd][q]
    float* Ks   = Qs + 64 * PQK;         // [64][PQK]  transposed: Ks[dd][p]
    float* Vs   = Ks + 64 * PQK;         // [128][64]
    float* Ps   = Vs + 128 * 64;         // [128][PP]
    float* k0s  = Ps + 128 * PP;         // [64]
    float* v0s  = k0s + 64;              // [64]
    float* msks = v0s + 64;              // [128]

    const int b = blockIdx.x, h = blockIdx.y, n = blockIdx.z;
    const int tid = threadIdx.x;
    const int tx = tid & 15, ty = tid >> 4;

    const size_t nh = (size_t)n * HH + h;
    const float* Qb = Q + (nh * TT + (size_t)b * BS) * DD;
    const float* Kb = K + nh * TT * DD;
    const float* Vb = V + nh * TT * DD;
    const float* Mb = M + (size_t)n * TT;
    float*       Ob = O + (nh * TT + (size_t)b * BS) * DD;

    // ---- Stage Q tile transposed into smem; stage k0/v0 -------------------
    {
        const int r  = tid >> 4;
        const int c4 = (tid & 15) * 4;
        #pragma unroll
        for (int it = 0; it < 8; it++) {
            const int q = r + it * 16;
            float4 v = *(const float4*)(Qb + q * DD + c4);
            Qs[(c4 + 0) * PQK + q] = v.x;
            Qs[(c4 + 1) * PQK + q] = v.y;
            Qs[(c4 + 2) * PQK + q] = v.z;
            Qs[(c4 + 3) * PQK + q] = v.w;
        }
    }
    if (tid < 64)       k0s[tid]      = Kb[tid];
    else if (tid < 128) v0s[tid - 64] = Vb[tid - 64];
    __syncthreads();

    float m[8], l[8];
    u64t acc2[8][2];     // packed output accumulators: dims (tx*4+0,+1) and (+2,+3)

    // ---- Init online softmax with the global key (key 0, mask 0) ----------
    {
        u64t s02[4];
        #pragma unroll
        for (int i2 = 0; i2 < 4; i2++) s02[i2] = pack2(0.f, 0.f);
        #pragma unroll 4
        for (int dd = 0; dd < 64; dd++) {
            const u64t k2 = pack2(k0s[dd], k0s[dd]);
            const u64t* qr = (const u64t*)(Qs + dd * PQK + ty * 8);
            #pragma unroll
            for (int i2 = 0; i2 < 4; i2++) fma2(s02[i2], qr[i2], k2);
        }
        const u64t va = *(const u64t*)(v0s + tx * 4);
        const u64t vb = *(const u64t*)(v0s + tx * 4 + 2);
        #pragma unroll
        for (int i2 = 0; i2 < 4; i2++) {
            float lo, hi;
            unpack2(s02[i2], lo, hi);
            m[2 * i2]     = lo * 0.125f;
            m[2 * i2 + 1] = hi * 0.125f;
        }
        #pragma unroll
        for (int i = 0; i < 8; i++) {
            l[i] = 1.f;
            acc2[i][0] = va;
            acc2[i][1] = vb;
        }
    }

    // ---- 3 key tiles: blocks b-1, b, b+1 ----------------------------------
    for (int kt = 0; kt < 3; kt++) {
        const int blk = b + kt - 1;
        if (blk < 0 || blk >= NB) continue;
        const int p0 = blk * BS;

        // load K tile (transposed) + V tile + mask row
        {
            const int r  = tid >> 4;
            const int c4 = (tid & 15) * 4;
            #pragma unroll
            for (int it = 0; it < 8; it++) {
                const int p = r + it * 16;
                float4 kv = *(const float4*)(Kb + (size_t)(p0 + p) * DD + c4);
                Ks[(c4 + 0) * PQK + p] = kv.x;
                Ks[(c4 + 1) * PQK + p] = kv.y;
                Ks[(c4 + 2) * PQK + p] = kv.z;
                Ks[(c4 + 3) * PQK + p] = kv.w;
                float4 vv = *(const float4*)(Vb + (size_t)(p0 + p) * DD + c4);
                *(float4*)(Vs + p * 64 + c4) = vv;
            }
        }
        if (tid < 128) {
            const int p = p0 + tid;
            msks[tid] = (p == 0) ? NEGV : Mb[p];
        }
        __syncthreads();

        // S = Q K^T, packed over query pairs: s2[i2][j] = (q=2i2, q=2i2+1)
        u64t s2[4][8];
        #pragma unroll
        for (int i2 = 0; i2 < 4; i2++)
            #pragma unroll
            for (int j = 0; j < 8; j++) s2[i2][j] = pack2(0.f, 0.f);

        #pragma unroll 4
        for (int dd = 0; dd < 64; dd++) {
            const u64t* qr = (const u64t*)(Qs + dd * PQK + ty * 8);
            const float* kr = Ks + dd * PQK + tx;
            u64t a[4], b2[8];
            #pragma unroll
            for (int i2 = 0; i2 < 4; i2++) a[i2] = qr[i2];
            #pragma unroll
            for (int j = 0; j < 8; j++) {
                const float kb_ = kr[16 * j];
                b2[j] = pack2(kb_, kb_);
            }
            #pragma unroll
            for (int i2 = 0; i2 < 4; i2++)
                #pragma unroll
                for (int j = 0; j < 8; j++) fma2(s2[i2][j], a[i2], b2[j]);
        }

        // unpack to scalar scores
        float s[8][8];
        #pragma unroll
        for (int i2 = 0; i2 < 4; i2++)
            #pragma unroll
            for (int j = 0; j < 8; j++)
                unpack2(s2[i2][j], s[2 * i2][j], s[2 * i2 + 1][j]);

        float mk[8];
        #pragma unroll
        for (int j = 0; j < 8; j++) mk[j] = msks[tx + 16 * j];

        // scale + mask + online softmax update + write P tile
        #pragma unroll
        for (int i = 0; i < 8; i++) {
            float tmax = NEGV;
            #pragma unroll
            for (int j = 0; j < 8; j++) {
                s[i][j] = s[i][j] * 0.125f + mk[j];
                tmax = fmaxf(tmax, s[i][j]);
            }
            #pragma unroll
            for (int o = 1; o < 16; o <<= 1)
                tmax = fmaxf(tmax, __shfl_xor_sync(0xffffffffu, tmax, o));
            const float mn   = fmaxf(m[i], tmax);
            const float corr = __expf(m[i] - mn);
            float rs = 0.f;
            #pragma unroll
            for (int j = 0; j < 8; j++) {
                const float p_ = __expf(s[i][j] - mn);
                s[i][j] = p_;
                rs += p_;
            }
            #pragma unroll
            for (int o = 1; o < 16; o <<= 1)
                rs += __shfl_xor_sync(0xffffffffu, rs, o);
            l[i] = l[i] * corr + rs;
            m[i] = mn;
            const u64t c2 = pack2(corr, corr);
            mul2(acc2[i][0], c2);
            mul2(acc2[i][1], c2);
            float* pr = Ps + (ty * 8 + i) * PP + tx;
            #pragma unroll
            for (int j = 0; j < 8; j++) pr[16 * j] = s[i][j];
        }
        __syncthreads();

        // O += P V, packed over dim pairs
        #pragma unroll 4
        for (int kk = 0; kk < 128; kk++) {
            const u64t* vp = (const u64t*)(Vs + kk * 64 + tx * 4);
            const u64t v0 = vp[0], v1 = vp[1];
            const float* pc = Ps + (ty * 8) * PP + kk;
            #pragma unroll
            for (int i = 0; i < 8; i++) {
                const float pp = pc[i * PP];
                const u64t p2 = pack2(pp, pp);
                fma2(acc2[i][0], p2, v0);
                fma2(acc2[i][1], p2, v1);
            }
        }
        __syncthreads();
    }

    // ---- epilogue ----------------------------------------------------------
    #pragma unroll
    for (int i = 0; i < 8; i++) {
        const float inv = 1.f / l[i];
        float a0, a1, a2_, a3;
        unpack2(acc2[i][0], a0, a1);
        unpack2(acc2[i][1], a2_, a3);
        float4 o4 = make_float4(a0 * inv, a1 * inv, a2_ * inv, a3 * inv);
        *(float4*)(Ob + (ty * 8 + i) * DD + tx * 4) = o4;
    }
}

// ---------------------------------------------------------------------------
// Kernel 2a: global row partials. Grid (NCH, HH, NN), 128 threads.
// Each CTA: 128-key chunk of softmax(q0 K^T * scale + mask) V, unnormalized,
// with chunk-local max. Writes (m, l, acc[64]) to g_part.
// ---------------------------------------------------------------------------
__global__ __launch_bounds__(128)
void bla_global_partial(const float* __restrict__ Q, const float* __restrict__ K,
                        const float* __restrict__ V, const float* __restrict__ M)
{
    __shared__ float Ksm[128 * 65];    // K chunk, pitch 65 (conflict-free dot)
    __shared__ float q0[64];
    __shared__ float sc[128];
    __shared__ float red[128];
    __shared__ float accs[2][64];

    const int ch = blockIdx.x, h = blockIdx.y, n = blockIdx.z;
    const int tid = threadIdx.x;
    const size_t nh = (size_t)n * HH + h;
    const int p0 = ch * 128;
    const float* Qb = Q + nh * TT * DD;
    const float* Kb = K + nh * TT * DD;
    const float* Vb = V + nh * TT * DD;
    const float* Mb = M + (size_t)n * TT;

    if (tid < 64) q0[tid] = Qb[tid];

    // stage K chunk (coalesced float4)
    for (int idx = tid; idx < 128 * 16; idx += 128) {
        const int row = idx >> 4;
        const int c4  = (idx & 15) * 4;
        float4 v = *(const float4*)(Kb + (size_t)(p0 + row) * DD + c4);
        Ksm[row * 65 + c4 + 0] = v.x;
        Ksm[row * 65 + c4 + 1] = v.y;
        Ksm[row * 65 + c4 + 2] = v.z;
        Ksm[row * 65 + c4 + 3] = v.w;
    }
    __syncthreads();

    // scores: one key per thread
    {
        float x = 0.f;
        const float* kr = Ksm + tid * 65;
        #pragma unroll 8
        for (int dd = 0; dd < 64; dd++) x += q0[dd] * kr[dd];
        sc[tid] = x * 0.125f + Mb[p0 + tid];
    }
    __syncthreads();

    // chunk max
    red[tid] = sc[tid]; __syncthreads();
    for (int s = 64; s; s >>= 1) {
        if (tid < s) red[tid] = fmaxf(red[tid], red[tid + s]);
        __syncthreads();
    }
    const float mx = red[0];
    __syncthreads();

    // exp + sum
    const float e = __expf(sc[tid] - mx);
    sc[tid] = e;
    red[tid] = e; __syncthreads();
    for (int s = 64; s; s >>= 1) {
        if (tid < s) red[tid] += red[tid + s];
        __syncthreads();
    }
    const float lsum = red[0];

    // partial PV from global (coalesced): thread t -> dim t&63, half t>>6
    {
        const int dd = tid & 63, seg = tid >> 6;
        float a = 0.f;
        #pragma unroll 8
        for (int pl = seg * 64; pl < seg * 64 + 64; pl++)
            a += sc[pl] * Vb[(size_t)(p0 + pl) * DD + dd];
        accs[seg][dd] = a;
    }
    __syncthreads();

    float* gp = g_part + (nh * NCH + ch) * 66;
    if (tid == 0) { gp[0] = mx; gp[1] = lsum; }
    if (tid < 64) gp[2 + tid] = accs[0][tid] + accs[1][tid];
}

// ---------------------------------------------------------------------------
// Kernel 2b: combine partials -> O[n,h,0,:]. Grid (HH, NN), 64 threads.
// ---------------------------------------------------------------------------
__global__ __launch_bounds__(64)
void bla_global_combine(float* __restrict__ O)
{
    const int h = blockIdx.x, n = blockIdx.y;
    const int d = threadIdx.x;
    const size_t nh = (size_t)n * HH + h;
    const float* gp = g_part + nh * NCH * 66;

    float mg = NEGV;
    #pragma unroll
    for (int c = 0; c < NCH; c++) mg = fmaxf(mg, gp[c * 66 + 0]);

    float lg = 0.f, og = 0.f;
    #pragma unroll
    for (int c = 0; c < NCH; c++) {
        const float w = __expf(gp[c * 66 + 0] - mg);
        lg += gp[c * 66 + 1] * w;
        og += gp[c * 66 + 2 + d] * w;
    }
    O[nh * TT * DD + d] = og / lg;
}

// ---------------------------------------------------------------------------
extern "C" void kernel_launch(void* const* d_in, const int* in_sizes, int n_in,
                              void* d_out, int out_size)
{
    (void)in_sizes; (void)n_in; (void)out_size;
    const float* Q = (const float*)d_in[0];
    const float* K = (const float*)d_in[1];
    const float* V = (const float*)d_in[2];
    const float* M = (const float*)d_in[3];
    float* O = (float*)d_out;

    const size_t smem = SMEM_FLOATS * sizeof(float);   // ~167 KB
    cudaFuncSetAttribute(bla_local_kernel,
                         cudaFuncAttributeMaxDynamicSharedMemorySize, (int)smem);

    bla_local_kernel<<<dim3(NB, HH, NN), 256, smem>>>(Q, K, V, M, O);
    bla_global_partial<<<dim3(NCH, HH, NN), 128>>>(Q, K, V, M);
    bla_global_combine<<<dim3(HH, NN), 64>>>(O);
}

// round 5
// speedup vs baseline: 2.8439x; 1.6162x over previous
#include <cuda_runtime.h>
#include <cuda_bf16.h>
#include <stdint.h>

#define NN 2
#define HH 16
#define TT 4096
#define DD 64
#define BS 128
#define NB 32
#define NCH 32
#define NEGV -3.402823466e38f

#define PK  72      // K smem pitch (bf16 elems): 144B rows -> banks 4*grp+tg, conflict-free
#define PVT 136     // Vt smem pitch (bf16 elems): 272B rows -> banks 4*grp+tg, conflict-free

// smem byte offsets
#define OFF_KHI  0                          // 128 x PK bf16 = 18432
#define OFF_KLO  18432
#define OFF_VTHI 36864                      // 64 x PVT bf16 = 17408
#define OFF_VTLO 54272
#define OFF_MSK  71680                      // 128 f32
#define OFF_K0   72192                      // 64 f32
#define OFF_V0   72448                      // 64 f32
#define SMEM_BYTES 73728

typedef unsigned int u32;
typedef unsigned long long u64;

__device__ float g_part[NN * HH * NCH * 66];

// ---- helpers ---------------------------------------------------------------
__device__ __forceinline__ u32 packsplit_hi(float a, float b) {
    __nv_bfloat16 ah = __float2bfloat16(a), bh = __float2bfloat16(b);
    return (u32)__bfloat16_as_ushort(ah) | ((u32)__bfloat16_as_ushort(bh) << 16);
}
__device__ __forceinline__ u32 packsplit_lo(float a, float b) {
    __nv_bfloat16 ah = __float2bfloat16(a), bh = __float2bfloat16(b);
    __nv_bfloat16 al = __float2bfloat16(a - __bfloat162float(ah));
    __nv_bfloat16 bl = __float2bfloat16(b - __bfloat162float(bh));
    return (u32)__bfloat16_as_ushort(al) | ((u32)__bfloat16_as_ushort(bl) << 16);
}
__device__ __forceinline__ void mma16816(float* c, const u32* a, u32 b0, u32 b1) {
    asm("mma.sync.aligned.m16n8k16.row.col.f32.bf16.bf16.f32 "
        "{%0,%1,%2,%3}, {%4,%5,%6,%7}, {%8,%9}, {%0,%1,%2,%3};"
        : "+f"(c[0]), "+f"(c[1]), "+f"(c[2]), "+f"(c[3])
        : "r"(a[0]), "r"(a[1]), "r"(a[2]), "r"(a[3]), "r"(b0), "r"(b1));
}
__device__ __forceinline__ float quad_max(float v) {
    v = fmaxf(v, __shfl_xor_sync(0xffffffffu, v, 1));
    v = fmaxf(v, __shfl_xor_sync(0xffffffffu, v, 2));
    return v;
}
__device__ __forceinline__ float quad_sum(float v) {
    v += __shfl_xor_sync(0xffffffffu, v, 1);
    v += __shfl_xor_sync(0xffffffffu, v, 2);
    return v;
}

// ---------------------------------------------------------------------------
// Block-local attention via mma.sync bf16-split. One CTA per (block,head,batch),
// 256 threads = 8 warps; warp w owns query rows [w*16, w*16+16).
// Lane: grp = lane>>2 (row within m16 tile), tg = lane&3.
// ---------------------------------------------------------------------------
__global__ __launch_bounds__(256, 1)
void bla_local_mma(const float* __restrict__ Q, const float* __restrict__ K,
                   const float* __restrict__ V, const float* __restrict__ M,
                   float* __restrict__ O)
{
    extern __shared__ char sb[];
    __nv_bfloat16* KHI  = (__nv_bfloat16*)(sb + OFF_KHI);
    __nv_bfloat16* KLO  = (__nv_bfloat16*)(sb + OFF_KLO);
    __nv_bfloat16* VTHI = (__nv_bfloat16*)(sb + OFF_VTHI);
    __nv_bfloat16* VTLO = (__nv_bfloat16*)(sb + OFF_VTLO);
    float* msk = (float*)(sb + OFF_MSK);
    float* K0s = (float*)(sb + OFF_K0);
    float* V0s = (float*)(sb + OFF_V0);

    const int b = blockIdx.x, h = blockIdx.y, n = blockIdx.z;
    const int tid = threadIdx.x;
    const int wid = tid >> 5, lane = tid & 31;
    const int grp = lane >> 2, tg = lane & 3;
    const int r0 = wid * 16 + grp;       // query row within block; r1 = r0+8

    const size_t nh = (size_t)n * HH + h;
    const float* Qb = Q + (nh * TT + (size_t)b * BS) * DD;
    const float* Kb = K + nh * TT * DD;
    const float* Vb = V + nh * TT * DD;
    const float* Mb = M + (size_t)n * TT;
    float*       Ob = O + (nh * TT + (size_t)b * BS) * DD;

    // ---- stage global key/value row 0 -------------------------------------
    if (tid < 64)       K0s[tid]      = Kb[tid];
    else if (tid < 128) V0s[tid - 64] = Vb[tid - 64];
    __syncthreads();

    // ---- Q fragments (scaled, bf16-split) + prologue dot with key 0 -------
    u32 qhi[4][4], qlo[4][4];
    float s0a = 0.f, s0b = 0.f;
    #pragma unroll
    for (int kk = 0; kk < 4; kk++) {
        const int c0 = kk * 16 + tg * 2;
        const int c1 = c0 + 8;
        float2 x0 = *(const float2*)(Qb + (size_t)r0 * DD + c0);
        float2 x1 = *(const float2*)(Qb + (size_t)r0 * DD + c1);
        float2 y0 = *(const float2*)(Qb + (size_t)(r0 + 8) * DD + c0);
        float2 y1 = *(const float2*)(Qb + (size_t)(r0 + 8) * DD + c1);
        x0.x *= 0.125f; x0.y *= 0.125f; x1.x *= 0.125f; x1.y *= 0.125f;
        y0.x *= 0.125f; y0.y *= 0.125f; y1.x *= 0.125f; y1.y *= 0.125f;
        s0a += x0.x * K0s[c0] + x0.y * K0s[c0+1] + x1.x * K0s[c1] + x1.y * K0s[c1+1];
        s0b += y0.x * K0s[c0] + y0.y * K0s[c0+1] + y1.x * K0s[c1] + y1.y * K0s[c1+1];
        qhi[kk][0] = packsplit_hi(x0.x, x0.y); qlo[kk][0] = packsplit_lo(x0.x, x0.y);
        qhi[kk][1] = packsplit_hi(y0.x, y0.y); qlo[kk][1] = packsplit_lo(y0.x, y0.y);
        qhi[kk][2] = packsplit_hi(x1.x, x1.y); qlo[kk][2] = packsplit_lo(x1.x, x1.y);
        qhi[kk][3] = packsplit_hi(y1.x, y1.y); qlo[kk][3] = packsplit_lo(y1.x, y1.y);
    }
    s0a = quad_sum(s0a);
    s0b = quad_sum(s0b);

    // ---- init online softmax with global key (mask 0, weight e^0 = 1) -----
    float m0 = s0a, m1 = s0b, l0 = 1.f, l1 = 1.f;
    float o[8][4];
    #pragma unroll
    for (int nt = 0; nt < 8; nt++) {
        const float va = V0s[nt * 8 + tg * 2], vb = V0s[nt * 8 + tg * 2 + 1];
        o[nt][0] = va; o[nt][1] = vb; o[nt][2] = va; o[nt][3] = vb;
    }

    // ---- 3 key blocks: b-1, b, b+1 ----------------------------------------
    for (int kt = 0; kt < 3; kt++) {
        const int blk = b + kt - 1;
        if (blk < 0 || blk >= NB) continue;
        const int p0 = blk * BS;
        __syncthreads();   // previous subtile reads done before restaging

        // stage K (row-major split) and V^T (dim-major split)
        #pragma unroll 2
        for (int i4 = tid; i4 < 2048; i4 += 256) {
            const int kr = i4 >> 4, d4 = (i4 & 15) << 2;
            float4 t = *(const float4*)(Kb + (size_t)(p0 + kr) * DD + d4);
            const u32 koff = (u32)kr * PK + (u32)d4;
            *(u64*)(KHI + koff) = (u64)packsplit_hi(t.x, t.y)
                                | ((u64)packsplit_hi(t.z, t.w) << 32);
            *(u64*)(KLO + koff) = (u64)packsplit_lo(t.x, t.y)
                                | ((u64)packsplit_lo(t.z, t.w) << 32);
            float4 v = *(const float4*)(Vb + (size_t)(p0 + kr) * DD + d4);
            float e[4] = {v.x, v.y, v.z, v.w};
            #pragma unroll
            for (int q = 0; q < 4; q++) {
                const u32 voff = (u32)(d4 + q) * PVT + (u32)kr;
                __nv_bfloat16 hi = __float2bfloat16(e[q]);
                VTHI[voff] = hi;
                VTLO[voff] = __float2bfloat16(e[q] - __bfloat162float(hi));
            }
        }
        if (tid < 128) {
            const int p = p0 + tid;
            msk[tid] = (p == 0) ? NEGV : Mb[p];
        }
        __syncthreads();

        // two 64-key subtiles
        #pragma unroll
        for (int st = 0; st < 2; st++) {
            const int ks0 = st * 64;

            // S = Q K^T (3 split terms)
            float sc[8][4];
            #pragma unroll
            for (int nt = 0; nt < 8; nt++)
                sc[nt][0] = sc[nt][1] = sc[nt][2] = sc[nt][3] = 0.f;
            #pragma unroll
            for (int kk = 0; kk < 4; kk++) {
                #pragma unroll
                for (int nt = 0; nt < 8; nt++) {
                    const u32 off = (u32)(ks0 + nt * 8 + grp) * PK + (u32)(kk * 16 + tg * 2);
                    const u32 bh0 = *(const u32*)(KHI + off);
                    const u32 bh1 = *(const u32*)(KHI + off + 8);
                    const u32 bl0 = *(const u32*)(KLO + off);
                    const u32 bl1 = *(const u32*)(KLO + off + 8);
                    mma16816(sc[nt], qhi[kk], bh0, bh1);
                    mma16816(sc[nt], qhi[kk], bl0, bl1);
                    mma16816(sc[nt], qlo[kk], bh0, bh1);
                }
            }

            // mask + row max
            float mx0 = NEGV, mx1 = NEGV;
            #pragma unroll
            for (int nt = 0; nt < 8; nt++) {
                const float mk0 = msk[ks0 + nt * 8 + tg * 2];
                const float mk1 = msk[ks0 + nt * 8 + tg * 2 + 1];
                sc[nt][0] += mk0; sc[nt][1] += mk1;
                sc[nt][2] += mk0; sc[nt][3] += mk1;
                mx0 = fmaxf(mx0, fmaxf(sc[nt][0], sc[nt][1]));
                mx1 = fmaxf(mx1, fmaxf(sc[nt][2], sc[nt][3]));
            }
            mx0 = quad_max(mx0); mx1 = quad_max(mx1);
            const float mn0 = fmaxf(m0, mx0), mn1 = fmaxf(m1, mx1);
            const float cr0 = __expf(m0 - mn0), cr1 = __expf(m1 - mn1);

            // exp + row sum; rescale O accumulators
            float ls0 = 0.f, ls1 = 0.f;
            #pragma unroll
            for (int nt = 0; nt < 8; nt++) {
                sc[nt][0] = __expf(sc[nt][0] - mn0); ls0 += sc[nt][0];
                sc[nt][1] = __expf(sc[nt][1] - mn0); ls0 += sc[nt][1];
                sc[nt][2] = __expf(sc[nt][2] - mn1); ls1 += sc[nt][2];
                sc[nt][3] = __expf(sc[nt][3] - mn1); ls1 += sc[nt][3];
            }
            ls0 = quad_sum(ls0); ls1 = quad_sum(ls1);
            l0 = l0 * cr0 + ls0; l1 = l1 * cr1 + ls1;
            m0 = mn0; m1 = mn1;
            #pragma unroll
            for (int nt = 0; nt < 8; nt++) {
                o[nt][0] *= cr0; o[nt][1] *= cr0;
                o[nt][2] *= cr1; o[nt][3] *= cr1;
            }

            // O += P V (P frags are register re-packs of S frags; 3 split terms)
            #pragma unroll
            for (int kk2 = 0; kk2 < 4; kk2++) {
                u32 ph[4], pl[4];
                ph[0] = packsplit_hi(sc[2*kk2][0],   sc[2*kk2][1]);
                pl[0] = packsplit_lo(sc[2*kk2][0],   sc[2*kk2][1]);
                ph[1] = packsplit_hi(sc[2*kk2][2],   sc[2*kk2][3]);
                pl[1] = packsplit_lo(sc[2*kk2][2],   sc[2*kk2][3]);
                ph[2] = packsplit_hi(sc[2*kk2+1][0], sc[2*kk2+1][1]);
                pl[2] = packsplit_lo(sc[2*kk2+1][0], sc[2*kk2+1][1]);
                ph[3] = packsplit_hi(sc[2*kk2+1][2], sc[2*kk2+1][3]);
                pl[3] = packsplit_lo(sc[2*kk2+1][2], sc[2*kk2+1][3]);
                #pragma unroll
                for (int nt = 0; nt < 8; nt++) {
                    const u32 off = (u32)(nt * 8 + grp) * PVT
                                  + (u32)(ks0 + kk2 * 16 + tg * 2);
                    const u32 bh0 = *(const u32*)(VTHI + off);
                    const u32 bh1 = *(const u32*)(VTHI + off + 8);
                    const u32 bl0 = *(const u32*)(VTLO + off);
                    const u32 bl1 = *(const u32*)(VTLO + off + 8);
                    mma16816(o[nt], ph, bh0, bh1);
                    mma16816(o[nt], ph, bl0, bl1);
                    mma16816(o[nt], pl, bh0, bh1);
                }
            }
        }
    }

    // ---- epilogue ----------------------------------------------------------
    const float inv0 = 1.f / l0, inv1 = 1.f / l1;
    #pragma unroll
    for (int nt = 0; nt < 8; nt++) {
        float2 w0 = make_float2(o[nt][0] * inv0, o[nt][1] * inv0);
        float2 w1 = make_float2(o[nt][2] * inv1, o[nt][3] * inv1);
        *(float2*)(Ob + (size_t)r0 * DD + nt * 8 + tg * 2) = w0;
        *(float2*)(Ob + (size_t)(r0 + 8) * DD + nt * 8 + tg * 2) = w1;
    }
}

// ---------------------------------------------------------------------------
// Global row split-K (unchanged — measured ~20us total)
// ---------------------------------------------------------------------------
__global__ __launch_bounds__(128)
void bla_global_partial(const float* __restrict__ Q, const float* __restrict__ K,
                        const float* __restrict__ V, const float* __restrict__ M)
{
    __shared__ float Ksm[128 * 65];
    __shared__ float q0[64];
    __shared__ float sc[128];
    __shared__ float red[128];
    __shared__ float accs[2][64];

    const int ch = blockIdx.x, h = blockIdx.y, n = blockIdx.z;
    const int tid = threadIdx.x;
    const size_t nh = (size_t)n * HH + h;
    const int p0 = ch * 128;
    const float* Qb = Q + nh * TT * DD;
    const float* Kb = K + nh * TT * DD;
    const float* Vb = V + nh * TT * DD;
    const float* Mb = M + (size_t)n * TT;

    if (tid < 64) q0[tid] = Qb[tid];
    for (int idx = tid; idx < 128 * 16; idx += 128) {
        const int row = idx >> 4;
        const int c4  = (idx & 15) * 4;
        float4 v = *(const float4*)(Kb + (size_t)(p0 + row) * DD + c4);
        Ksm[row * 65 + c4 + 0] = v.x; Ksm[row * 65 + c4 + 1] = v.y;
        Ksm[row * 65 + c4 + 2] = v.z; Ksm[row * 65 + c4 + 3] = v.w;
    }
    __syncthreads();
    {
        float x = 0.f;
        const float* kr = Ksm + tid * 65;
        #pragma unroll 8
        for (int dd = 0; dd < 64; dd++) x += q0[dd] * kr[dd];
        sc[tid] = x * 0.125f + Mb[p0 + tid];
    }
    __syncthreads();
    red[tid] = sc[tid]; __syncthreads();
    for (int s = 64; s; s >>= 1) {
        if (tid < s) red[tid] = fmaxf(red[tid], red[tid + s]);
        __syncthreads();
    }
    const float mx = red[0];
    __syncthreads();
    const float e = __expf(sc[tid] - mx);
    sc[tid] = e;
    red[tid] = e; __syncthreads();
    for (int s = 64; s; s >>= 1) {
        if (tid < s) red[tid] += red[tid + s];
        __syncthreads();
    }
    const float lsum = red[0];
    {
        const int dd = tid & 63, seg = tid >> 6;
        float a = 0.f;
        #pragma unroll 8
        for (int pl = seg * 64; pl < seg * 64 + 64; pl++)
            a += sc[pl] * Vb[(size_t)(p0 + pl) * DD + dd];
        accs[seg][dd] = a;
    }
    __syncthreads();
    float* gp = g_part + (nh * NCH + ch) * 66;
    if (tid == 0) { gp[0] = mx; gp[1] = lsum; }
    if (tid < 64) gp[2 + tid] = accs[0][tid] + accs[1][tid];
}

__global__ __launch_bounds__(64)
void bla_global_combine(float* __restrict__ O)
{
    const int h = blockIdx.x, n = blockIdx.y;
    const int d = threadIdx.x;
    const size_t nh = (size_t)n * HH + h;
    const float* gp = g_part + nh * NCH * 66;

    float mg = NEGV;
    #pragma unroll
    for (int c = 0; c < NCH; c++) mg = fmaxf(mg, gp[c * 66 + 0]);
    float lg = 0.f, og = 0.f;
    #pragma unroll
    for (int c = 0; c < NCH; c++) {
        const float w = __expf(gp[c * 66 + 0] - mg);
        lg += gp[c * 66 + 1] * w;
        og += gp[c * 66 + 2 + d] * w;
    }
    O[nh * TT * DD + d] = og / lg;
}

// ---------------------------------------------------------------------------
extern "C" void kernel_launch(void* const* d_in, const int* in_sizes, int n_in,
                              void* d_out, int out_size)
{
    (void)in_sizes; (void)n_in; (void)out_size;
    const float* Q = (const float*)d_in[0];
    const float* K = (const float*)d_in[1];
    const float* V = (const float*)d_in[2];
    const float* M = (const float*)d_in[3];
    float* O = (float*)d_out;

    cudaFuncSetAttribute(bla_local_mma,
                         cudaFuncAttributeMaxDynamicSharedMemorySize, SMEM_BYTES);

    bla_local_mma<<<dim3(NB, HH, NN), 256, SMEM_BYTES>>>(Q, K, V, M, O);
    bla_global_partial<<<dim3(NCH, HH, NN), 128>>>(Q, K, V, M);
    bla_global_combine<<<dim3(HH, NN), 64>>>(O);
}

// round 6
// speedup vs baseline: 3.4521x; 1.2139x over previous
#include <cuda_runtime.h>
#include <cuda_bf16.h>
#include <stdint.h>

#define NN 2
#define HH 16
#define TT 4096
#define DD 64
#define BS 128
#define NB 32
#define NCH 32
#define NEGV -3.402823466e38f
#define TOTE (NN*HH*TT*DD)      // 8388608 elements

#define PITCH 144               // smem row pitch in BYTES (72 bf16): banks 4r mod 32, 16B-aligned
#define PLANE (128*PITCH)       // 18432 B per plane tile
#define BUFSZ (4*PLANE)         // KHI,KLO,VHI,VLO
#define OFF_MSK (2*BUFSZ)       // 3*128 f32 = 1536
#define OFF_K0  (OFF_MSK + 1536)
#define OFF_V0  (OFF_K0 + 256)
#define SMEM_BYTES (OFF_V0 + 256)   // ~149.8 KB

typedef unsigned int u32;
typedef unsigned long long u64;

__device__ float g_part[NN * HH * NCH * 66];
__device__ __align__(16) __nv_bfloat16 gKhi[TOTE];
__device__ __align__(16) __nv_bfloat16 gKlo[TOTE];
__device__ __align__(16) __nv_bfloat16 gVhi[TOTE];
__device__ __align__(16) __nv_bfloat16 gVlo[TOTE];

// ---- helpers ---------------------------------------------------------------
__device__ __forceinline__ u32 packsplit_hi(float a, float b) {
    __nv_bfloat16 ah = __float2bfloat16(a), bh = __float2bfloat16(b);
    return (u32)__bfloat16_as_ushort(ah) | ((u32)__bfloat16_as_ushort(bh) << 16);
}
__device__ __forceinline__ u32 packsplit_lo(float a, float b) {
    __nv_bfloat16 ah = __float2bfloat16(a), bh = __float2bfloat16(b);
    __nv_bfloat16 al = __float2bfloat16(a - __bfloat162float(ah));
    __nv_bfloat16 bl = __float2bfloat16(b - __bfloat162float(bh));
    return (u32)__bfloat16_as_ushort(al) | ((u32)__bfloat16_as_ushort(bl) << 16);
}
__device__ __forceinline__ void mma16816(float* c, const u32* a, u32 b0, u32 b1) {
    asm("mma.sync.aligned.m16n8k16.row.col.f32.bf16.bf16.f32 "
        "{%0,%1,%2,%3}, {%4,%5,%6,%7}, {%8,%9}, {%0,%1,%2,%3};"
        : "+f"(c[0]), "+f"(c[1]), "+f"(c[2]), "+f"(c[3])
        : "r"(a[0]), "r"(a[1]), "r"(a[2]), "r"(a[3]), "r"(b0), "r"(b1));
}
__device__ __forceinline__ void ldsm4(u32 a, u32& r0, u32& r1, u32& r2, u32& r3) {
    asm volatile("ldmatrix.sync.aligned.m8n8.x4.shared.b16 {%0,%1,%2,%3}, [%4];"
                 : "=r"(r0), "=r"(r1), "=r"(r2), "=r"(r3) : "r"(a));
}
__device__ __forceinline__ void ldsm4t(u32 a, u32& r0, u32& r1, u32& r2, u32& r3) {
    asm volatile("ldmatrix.sync.aligned.m8n8.x4.trans.shared.b16 {%0,%1,%2,%3}, [%4];"
                 : "=r"(r0), "=r"(r1), "=r"(r2), "=r"(r3) : "r"(a));
}
__device__ __forceinline__ void cp16(u32 dst, const void* src) {
    asm volatile("cp.async.ca.shared.global [%0], [%1], 16;" :: "r"(dst), "l"(src) : "memory");
}
#define CP_COMMIT() asm volatile("cp.async.commit_group;" ::: "memory")
#define CP_WAIT(n)  asm volatile("cp.async.wait_group %0;" :: "n"(n) : "memory")
__device__ __forceinline__ u32 smem_u32(const void* p) {
    u32 a;
    asm("{ .reg .u64 t; cvta.to.shared.u64 t, %1; cvt.u32.u64 %0, t; }" : "=r"(a) : "l"(p));
    return a;
}
__device__ __forceinline__ float quad_max(float v) {
    v = fmaxf(v, __shfl_xor_sync(0xffffffffu, v, 1));
    v = fmaxf(v, __shfl_xor_sync(0xffffffffu, v, 2));
    return v;
}
__device__ __forceinline__ float quad_sum(float v) {
    v += __shfl_xor_sync(0xffffffffu, v, 1);
    v += __shfl_xor_sync(0xffffffffu, v, 2);
    return v;
}

// ---------------------------------------------------------------------------
// Kernel 0: split K and V into bf16 hi/lo planes (memory-bound, ~20us)
// ---------------------------------------------------------------------------
__global__ __launch_bounds__(256)
void split_kv(const float* __restrict__ K, const float* __restrict__ V)
{
    const int i = blockIdx.x * blockDim.x + threadIdx.x;   // float4 index
    if (i >= TOTE / 4) return;
    float4 k = ((const float4*)K)[i];
    float4 v = ((const float4*)V)[i];
    ((u64*)gKhi)[i] = (u64)packsplit_hi(k.x, k.y) | ((u64)packsplit_hi(k.z, k.w) << 32);
    ((u64*)gKlo)[i] = (u64)packsplit_lo(k.x, k.y) | ((u64)packsplit_lo(k.z, k.w) << 32);
    ((u64*)gVhi)[i] = (u64)packsplit_hi(v.x, v.y) | ((u64)packsplit_hi(v.z, v.w) << 32);
    ((u64*)gVlo)[i] = (u64)packsplit_lo(v.x, v.y) | ((u64)packsplit_lo(v.z, v.w) << 32);
}

// ---------------------------------------------------------------------------
// Kernel 1: block-local attention, mma.sync bf16-split + ldmatrix + cp.async.
// One CTA per (block,head,batch), 256 threads = 8 warps, 16 q-rows/warp.
// ---------------------------------------------------------------------------
__global__ __launch_bounds__(256, 1)
void bla_local_mma(const float* __restrict__ Q, const float* __restrict__ K,
                   const float* __restrict__ V, const float* __restrict__ M,
                   float* __restrict__ O)
{
    extern __shared__ char sb[];
    const u32 sb32 = smem_u32(sb);

    const int b = blockIdx.x, h = blockIdx.y, n = blockIdx.z;
    const int tid = threadIdx.x;
    const int wid = tid >> 5, lane = tid & 31;
    const int grp = lane >> 2, tg = lane & 3;
    const int r0 = wid * 16 + grp;

    // ldmatrix lane-address components
    const int lr    = lane & 7;
    const int lsub1 = ((lane >> 3) & 1) << 3;
    const int lsub2 = (lane >> 4);          // 0/1

    const size_t nh = (size_t)n * HH + h;
    const size_t kvbase = nh * TT * DD;
    const float* Qb = Q + (nh * TT + (size_t)b * BS) * DD;
    const float* Kb = K + kvbase;
    const float* Vb = V + kvbase;
    const float* Mb = M + (size_t)n * TT;
    float*       Ob = O + (nh * TT + (size_t)b * BS) * DD;

    float* mk  = (float*)(sb + OFF_MSK);
    float* K0s = (float*)(sb + OFF_K0);
    float* V0s = (float*)(sb + OFF_V0);

    // ---- async staging helper (lambda-free macro style) -------------------
    // plane sources for clamped block index
    auto stage = [&](int buf, int blkc) {
        const size_t base = kvbase + (size_t)blkc * BS * DD;
        const u32 d0 = sb32 + buf * BUFSZ;
        #pragma unroll
        for (int p = 0; p < 4; p++) {
            const __nv_bfloat16* src =
                (p == 0) ? gKhi + base : (p == 1) ? gKlo + base :
                (p == 2) ? gVhi + base : gVlo + base;
            const u32 dp = d0 + p * PLANE;
            #pragma unroll
            for (int c = tid; c < 1024; c += 256) {
                const int row = c >> 3, cc = c & 7;
                cp16(dp + row * PITCH + cc * 16, src + row * DD + cc * 8);
            }
        }
    };

    const int blk0 = b - 1, blk2 = b + 1;
    const int blk0c = blk0 < 0 ? 0 : blk0;
    const int blk2c = blk2 >= NB ? NB - 1 : blk2;

    stage(0, blk0c); CP_COMMIT();
    stage(1, b);     CP_COMMIT();

    // masks for all 3 blocks + global k0/v0 (regular loads)
    if (tid < 128) {
        #pragma unroll
        for (int kt = 0; kt < 3; kt++) {
            const int blk = b + kt - 1;
            float mval = NEGV;
            if (blk >= 0 && blk < NB) {
                const int p = blk * BS + tid;
                mval = (p == 0) ? NEGV : Mb[p];
            }
            mk[kt * 128 + tid] = mval;
        }
    } else if (tid < 192) K0s[tid - 128] = Kb[tid - 128];
    else                  V0s[tid - 192] = Vb[tid - 192];

    // ---- Q fragments (scaled, bf16-split) ---------------------------------
    u32 qhi[4][4], qlo[4][4];
    float qrow0[8], qrow1[8];   // this thread's Q elems for prologue dot
    #pragma unroll
    for (int kk = 0; kk < 4; kk++) {
        const int c0 = kk * 16 + tg * 2;
        const int c1 = c0 + 8;
        float2 x0 = *(const float2*)(Qb + (size_t)r0 * DD + c0);
        float2 x1 = *(const float2*)(Qb + (size_t)r0 * DD + c1);
        float2 y0 = *(const float2*)(Qb + (size_t)(r0 + 8) * DD + c0);
        float2 y1 = *(const float2*)(Qb + (size_t)(r0 + 8) * DD + c1);
        x0.x *= 0.125f; x0.y *= 0.125f; x1.x *= 0.125f; x1.y *= 0.125f;
        y0.x *= 0.125f; y0.y *= 0.125f; y1.x *= 0.125f; y1.y *= 0.125f;
        qrow0[2*kk] = x0.x; qrow0[2*kk+1] = x0.y;
        qrow1[2*kk] = y0.x; qrow1[2*kk+1] = y0.y;
        qhi[kk][0] = packsplit_hi(x0.x, x0.y); qlo[kk][0] = packsplit_lo(x0.x, x0.y);
        qhi[kk][1] = packsplit_hi(y0.x, y0.y); qlo[kk][1] = packsplit_lo(y0.x, y0.y);
        qhi[kk][2] = packsplit_hi(x1.x, x1.y); qlo[kk][2] = packsplit_lo(x1.x, x1.y);
        qhi[kk][3] = packsplit_hi(y1.x, y1.y); qlo[kk][3] = packsplit_lo(y1.x, y1.y);
        // stash the c1 elems too for the prologue dot
        qrow0[2*kk]   = x0.x;  // (c0,c0+1) handled below explicitly
        qrow1[2*kk]   = y0.x;
        qrow0[2*kk+1] = x0.y;
        qrow1[2*kk+1] = y0.y;
        // keep x1/y1 in regs via recompute in prologue loop instead
    }

    __syncthreads();   // K0s/V0s visible

    // prologue dot with global key 0 (fp32)
    float s0a = 0.f, s0b = 0.f;
    #pragma unroll
    for (int kk = 0; kk < 4; kk++) {
        const int c0 = kk * 16 + tg * 2;
        const int c1 = c0 + 8;
        // reload Q c1 elems (L1-hot) to save registers
        float2 x1 = *(const float2*)(Qb + (size_t)r0 * DD + c1);
        float2 y1 = *(const float2*)(Qb + (size_t)(r0 + 8) * DD + c1);
        s0a += qrow0[2*kk] * K0s[c0] + qrow0[2*kk+1] * K0s[c0+1]
             + 0.125f * (x1.x * K0s[c1] + x1.y * K0s[c1+1]);
        s0b += qrow1[2*kk] * K0s[c0] + qrow1[2*kk+1] * K0s[c0+1]
             + 0.125f * (y1.x * K0s[c1] + y1.y * K0s[c1+1]);
    }
    s0a = quad_sum(s0a);
    s0b = quad_sum(s0b);

    float m0 = s0a, m1 = s0b, l0 = 1.f, l1 = 1.f;
    float o[8][4];
    #pragma unroll
    for (int nt = 0; nt < 8; nt++) {
        const float va = V0s[nt * 8 + tg * 2], vb = V0s[nt * 8 + tg * 2 + 1];
        o[nt][0] = va; o[nt][1] = vb; o[nt][2] = va; o[nt][3] = vb;
    }

    // ---- compute one staged key block -------------------------------------
    auto compute = [&](int buf, const float* mb) {
        const u32 bKHI = sb32 + buf * BUFSZ;
        const u32 bKLO = bKHI + PLANE;
        const u32 bVHI = bKLO + PLANE;
        const u32 bVLO = bVHI + PLANE;

        #pragma unroll
        for (int st = 0; st < 2; st++) {
            const int ks0 = st * 64;

            float sc[8][4];
            #pragma unroll
            for (int nt = 0; nt < 8; nt++)
                sc[nt][0] = sc[nt][1] = sc[nt][2] = sc[nt][3] = 0.f;

            // S = Q K^T (3 split terms), ldmatrix x4 (2 nt per load)
            #pragma unroll
            for (int kk = 0; kk < 4; kk++) {
                #pragma unroll
                for (int ntp = 0; ntp < 4; ntp++) {
                    const u32 row = (u32)(ks0 + ntp * 16 + (lsub2 << 3) + lr);
                    const u32 col = (u32)((kk * 16 + lsub1) * 2);
                    u32 h0, h1, h2, h3, l0_, l1_, l2_, l3_;
                    ldsm4(bKHI + row * PITCH + col, h0, h1, h2, h3);
                    ldsm4(bKLO + row * PITCH + col, l0_, l1_, l2_, l3_);
                    mma16816(sc[2*ntp],   qhi[kk], h0, h1);
                    mma16816(sc[2*ntp],   qhi[kk], l0_, l1_);
                    mma16816(sc[2*ntp],   qlo[kk], h0, h1);
                    mma16816(sc[2*ntp+1], qhi[kk], h2, h3);
                    mma16816(sc[2*ntp+1], qhi[kk], l2_, l3_);
                    mma16816(sc[2*ntp+1], qlo[kk], h2, h3);
                }
            }

            // mask + online softmax
            float mx0 = NEGV, mx1 = NEGV;
            #pragma unroll
            for (int nt = 0; nt < 8; nt++) {
                const float mk0 = mb[ks0 + nt * 8 + tg * 2];
                const float mk1 = mb[ks0 + nt * 8 + tg * 2 + 1];
                sc[nt][0] += mk0; sc[nt][1] += mk1;
                sc[nt][2] += mk0; sc[nt][3] += mk1;
                mx0 = fmaxf(mx0, fmaxf(sc[nt][0], sc[nt][1]));
                mx1 = fmaxf(mx1, fmaxf(sc[nt][2], sc[nt][3]));
            }
            mx0 = quad_max(mx0); mx1 = quad_max(mx1);
            const float mn0 = fmaxf(m0, mx0), mn1 = fmaxf(m1, mx1);
            const float cr0 = __expf(m0 - mn0), cr1 = __expf(m1 - mn1);

            float ls0 = 0.f, ls1 = 0.f;
            #pragma unroll
            for (int nt = 0; nt < 8; nt++) {
                sc[nt][0] = __expf(sc[nt][0] - mn0); ls0 += sc[nt][0];
                sc[nt][1] = __expf(sc[nt][1] - mn0); ls0 += sc[nt][1];
                sc[nt][2] = __expf(sc[nt][2] - mn1); ls1 += sc[nt][2];
                sc[nt][3] = __expf(sc[nt][3] - mn1); ls1 += sc[nt][3];
            }
            ls0 = quad_sum(ls0); ls1 = quad_sum(ls1);
            l0 = l0 * cr0 + ls0; l1 = l1 * cr1 + ls1;
            m0 = mn0; m1 = mn1;
            #pragma unroll
            for (int nt = 0; nt < 8; nt++) {
                o[nt][0] *= cr0; o[nt][1] *= cr0;
                o[nt][2] *= cr1; o[nt][3] *= cr1;
            }

            // O += P V (3 split terms), V frags via ldmatrix.trans (2 nt per load)
            #pragma unroll
            for (int kk2 = 0; kk2 < 4; kk2++) {
                u32 ph[4], pl[4];
                ph[0] = packsplit_hi(sc[2*kk2][0],   sc[2*kk2][1]);
                pl[0] = packsplit_lo(sc[2*kk2][0],   sc[2*kk2][1]);
                ph[1] = packsplit_hi(sc[2*kk2][2],   sc[2*kk2][3]);
                pl[1] = packsplit_lo(sc[2*kk2][2],   sc[2*kk2][3]);
                ph[2] = packsplit_hi(sc[2*kk2+1][0], sc[2*kk2+1][1]);
                pl[2] = packsplit_lo(sc[2*kk2+1][0], sc[2*kk2+1][1]);
                ph[3] = packsplit_hi(sc[2*kk2+1][2], sc[2*kk2+1][3]);
                pl[3] = packsplit_lo(sc[2*kk2+1][2], sc[2*kk2+1][3]);
                #pragma unroll
                for (int ntp = 0; ntp < 4; ntp++) {
                    const u32 row = (u32)(ks0 + kk2 * 16 + lsub1 + lr);
                    const u32 col = (u32)(((ntp * 2 + lsub2) * 8) * 2);
                    u32 h0, h1, h2, h3, v0_, v1_, v2_, v3_;
                    ldsm4t(bVHI + row * PITCH + col, h0, h1, h2, h3);
                    ldsm4t(bVLO + row * PITCH + col, v0_, v1_, v2_, v3_);
                    mma16816(o[2*ntp],   ph, h0, h1);
                    mma16816(o[2*ntp],   ph, v0_, v1_);
                    mma16816(o[2*ntp],   pl, h0, h1);
                    mma16816(o[2*ntp+1], ph, h2, h3);
                    mma16816(o[2*ntp+1], ph, v2_, v3_);
                    mma16816(o[2*ntp+1], pl, h2, h3);
                }
            }
        }
    };

    // ---- pipelined 3-block loop -------------------------------------------
    CP_WAIT(1); __syncthreads();                 // buf0 ready
    if (blk0 >= 0) compute(0, mk);
    __syncthreads();                             // done reading buf0
    stage(0, blk2c); CP_COMMIT();
    CP_WAIT(1); __syncthreads();                 // buf1 ready
    compute(1, mk + 128);
    CP_WAIT(0); __syncthreads();                 // buf0 (block b+1) ready
    if (blk2 < NB) compute(0, mk + 256);

    // ---- epilogue ----------------------------------------------------------
    const float inv0 = 1.f / l0, inv1 = 1.f / l1;
    #pragma unroll
    for (int nt = 0; nt < 8; nt++) {
        float2 w0 = make_float2(o[nt][0] * inv0, o[nt][1] * inv0);
        float2 w1 = make_float2(o[nt][2] * inv1, o[nt][3] * inv1);
        *(float2*)(Ob + (size_t)r0 * DD + nt * 8 + tg * 2) = w0;
        *(float2*)(Ob + (size_t)(r0 + 8) * DD + nt * 8 + tg * 2) = w1;
    }
}

// ---------------------------------------------------------------------------
// Global row split-K (unchanged)
// ---------------------------------------------------------------------------
__global__ __launch_bounds__(128)
void bla_global_partial(const float* __restrict__ Q, const float* __restrict__ K,
                        const float* __restrict__ V, const float* __restrict__ M)
{
    __shared__ float Ksm[128 * 65];
    __shared__ float q0[64];
    __shared__ float sc[128];
    __shared__ float red[128];
    __shared__ float accs[2][64];

    const int ch = blockIdx.x, h = blockIdx.y, n = blockIdx.z;
    const int tid = threadIdx.x;
    const size_t nh = (size_t)n * HH + h;
    const int p0 = ch * 128;
    const float* Qb = Q + nh * TT * DD;
    const float* Kb = K + nh * TT * DD;
    const float* Vb = V + nh * TT * DD;
    const float* Mb = M + (size_t)n * TT;

    if (tid < 64) q0[tid] = Qb[tid];
    for (int idx = tid; idx < 128 * 16; idx += 128) {
        const int row = idx >> 4;
        const int c4  = (idx & 15) * 4;
        float4 v = *(const float4*)(Kb + (size_t)(p0 + row) * DD + c4);
        Ksm[row * 65 + c4 + 0] = v.x; Ksm[row * 65 + c4 + 1] = v.y;
        Ksm[row * 65 + c4 + 2] = v.z; Ksm[row * 65 + c4 + 3] = v.w;
    }
    __syncthreads();
    {
        float x = 0.f;
        const float* kr = Ksm + tid * 65;
        #pragma unroll 8
        for (int dd = 0; dd < 64; dd++) x += q0[dd] * kr[dd];
        sc[tid] = x * 0.125f + Mb[p0 + tid];
    }
    __syncthreads();
    red[tid] = sc[tid]; __syncthreads();
    for (int s = 64; s; s >>= 1) {
        if (tid < s) red[tid] = fmaxf(red[tid], red[tid + s]);
        __syncthreads();
    }
    const float mx = red[0];
    __syncthreads();
    const float e = __expf(sc[tid] - mx);
    sc[tid] = e;
    red[tid] = e; __syncthreads();
    for (int s = 64; s; s >>= 1) {
        if (tid < s) red[tid] += red[tid + s];
        __syncthreads();
    }
    const float lsum = red[0];
    {
        const int dd = tid & 63, seg = tid >> 6;
        float a = 0.f;
        #pragma unroll 8
        for (int pl = seg * 64; pl < seg * 64 + 64; pl++)
            a += sc[pl] * Vb[(size_t)(p0 + pl) * DD + dd];
        accs[seg][dd] = a;
    }
    __syncthreads();
    float* gp = g_part + (nh * NCH + ch) * 66;
    if (tid == 0) { gp[0] = mx; gp[1] = lsum; }
    if (tid < 64) gp[2 + tid] = accs[0][tid] + accs[1][tid];
}

__global__ __launch_bounds__(64)
void bla_global_combine(float* __restrict__ O)
{
    const int h = blockIdx.x, n = blockIdx.y;
    const int d = threadIdx.x;
    const size_t nh = (size_t)n * HH + h;
    const float* gp = g_part + nh * NCH * 66;

    float mg = NEGV;
    #pragma unroll
    for (int c = 0; c < NCH; c++) mg = fmaxf(mg, gp[c * 66 + 0]);
    float lg = 0.f, og = 0.f;
    #pragma unroll
    for (int c = 0; c < NCH; c++) {
        const float w = __expf(gp[c * 66 + 0] - mg);
        lg += gp[c * 66 + 1] * w;
        og += gp[c * 66 + 2 + d] * w;
    }
    O[nh * TT * DD + d] = og / lg;
}

// ---------------------------------------------------------------------------
extern "C" void kernel_launch(void* const* d_in, const int* in_sizes, int n_in,
                              void* d_out, int out_size)
{
    (void)in_sizes; (void)n_in; (void)out_size;
    const float* Q = (const float*)d_in[0];
    const float* K = (const float*)d_in[1];
    const float* V = (const float*)d_in[2];
    const float* M = (const float*)d_in[3];
    float* O = (float*)d_out;

    cudaFuncSetAttribute(bla_local_mma,
                         cudaFuncAttributeMaxDynamicSharedMemorySize, SMEM_BYTES);

    split_kv<<<(TOTE / 4 + 255) / 256, 256>>>(K, V);
    bla_local_mma<<<dim3(NB, HH, NN), 256, SMEM_BYTES>>>(Q, K, V, M, O);
    bla_global_partial<<<dim3(NCH, HH, NN), 128>>>(Q, K, V, M);
    bla_global_combine<<<dim3(HH, NN), 64>>>(O);
}